// round 4
// baseline (speedup 1.0000x reference)
#include <cuda_runtime.h>

#define NBATCH 64
#define NANCH  8400
#define KD     51
#define MAXDET 300
#define TPB    512
#define KPT    ((NANCH + TPB - 1) / TPB)   // 17

#define NBUCK   4096
#define KWANT   512
#define BANDCAP 1536
#define SORTCAP 2048
#define CHUNK   512
#define MASKW   8

#define SCORE_T 0.001f
#define IOU_T   0.7f

typedef unsigned long long u64;
typedef unsigned int u32;

// ----- global scratch (static __device__, no allocation) -----
__device__ u64    g_keys[NBATCH * SORTCAP];
__device__ float4 g_cbox[NBATCH * CHUNK];
__device__ float  g_carA[NBATCH * CHUNK];
__device__ u32    g_cmsk[NBATCH * CHUNK];
__device__ u64    g_mat [NBATCH * MASKW * CHUNK];   // [img][w][i]
__device__ int    g_len [NBATCH];
__device__ int    g_tbnd[NBATCH];

__device__ __forceinline__ u32 mono(float s) {
    u32 u = __float_as_uint(s);
    return (u & 0x80000000u) ? ~u : (u | 0x80000000u);
}

__device__ __forceinline__ bool sup_exact(float ix, float iy, float a_sel, float a_cand) {
    float inter = fmaxf(ix, 0.0f) * fmaxf(iy, 0.0f);
    float iou = inter / (a_sel + a_cand - inter + 1e-7f);
    return iou > IOU_T;
}

// conservative 16x + 16y cell occupancy mask (40px cells, clamped) — superset of overlap
__device__ __forceinline__ u32 cellmask(float4 bv) {
    int xa = (int)(bv.x * 0.025f); xa = max(0, min(15, xa));
    int xb = (int)(bv.z * 0.025f); xb = max(xa, min(15, xb));
    int ya = (int)(bv.y * 0.025f); ya = max(0, min(15, ya));
    int yb = (int)(bv.w * 0.025f); yb = max(ya, min(15, yb));
    u32 xm = ((2u << xb) - 1u) & ~((1u << xa) - 1u);
    u32 ym = ((2u << yb) - 1u) & ~((1u << ya) - 1u);
    return xm | (ym << 16);
}

// =======================================================================
// K1: per-image top-band select + bitonic sort; writes keys + chunk0 data
// =======================================================================
__global__ __launch_bounds__(TPB, 1)
void k1_select(const float* __restrict__ boxes, const float* __restrict__ scores)
{
    extern __shared__ unsigned char smraw[];
    u64* band      = (u64*)smraw;                 // [SORTCAP]
    u32* sfx       = (u32*)(band + SORTCAP);      // [NBUCK]
    u32* blocksum  = sfx + NBUCK;                 // [16]
    int* ctrl      = (int*)(blocksum + 16);

    const int b = blockIdx.x, tid = threadIdx.x, lane = tid & 31, wid = tid >> 5;
    const float* bb = boxes  + (size_t)b * NANCH * 4;
    const float* ss = scores + (size_t)b * NANCH;

    float rs[KPT]; int rbk[KPT];
    for (int i = tid; i < NBUCK; i += TPB) sfx[i] = 0u;
    __syncthreads();

    #pragma unroll
    for (int k = 0; k < KPT; k++) {
        int idx = tid + k * TPB;
        float s = (idx < NANCH) ? ss[idx] : 0.0f;
        rs[k] = s; int bk = -1;
        if (idx < NANCH && s > SCORE_T) {
            bk = min((int)(s * (float)NBUCK), NBUCK - 1);
            atomicAdd(&sfx[bk], 1u);
        }
        rbk[k] = bk;
    }
    __syncthreads();

    // suffix sums
    {
        u32 lsum[8]; u32 run = 0;
        const int base = tid * 8;
        #pragma unroll
        for (int j = 7; j >= 0; j--) { run += sfx[base + j]; lsum[j] = run; }
        u32 x = run;
        #pragma unroll
        for (int off = 1; off < 32; off <<= 1) {
            u32 o = __shfl_down_sync(0xFFFFFFFFu, x, off);
            if (lane + off < 32) x += o;
        }
        if (lane == 0) blocksum[wid] = x;
        __syncthreads();
        u32 woff = 0;
        for (int w = wid + 1; w < TPB / 32; w++) woff += blocksum[w];
        u32 excl = woff + (x - run);
        #pragma unroll
        for (int j = 0; j < 8; j++) sfx[base + j] = excl + lsum[j];
        __syncthreads();
    }

    // pick band0 lower bound tb
    if (tid == 0) {
        u32 total = sfx[0];
        int tb = NBUCK;
        if (total) {
            u32 want = total < (u32)KWANT ? total : (u32)KWANT;
            int lo = 0, hi = NBUCK - 1; tb = 0;
            while (lo <= hi) { int m = (lo + hi) >> 1; if (sfx[m] >= want) { tb = m; lo = m + 1; } else hi = m - 1; }
            if (sfx[tb] > (u32)BANDCAP) {
                int lo2 = tb + 1, hi2 = NBUCK - 1, nb = NBUCK - 1;
                while (lo2 <= hi2) { int m = (lo2 + hi2) >> 1; if (sfx[m] <= (u32)BANDCAP) { nb = m; hi2 = m - 1; } else lo2 = m + 1; }
                tb = nb;
            }
        }
        ctrl[0] = 0; ctrl[1] = tb;
        g_tbnd[b] = tb;
    }
    __syncthreads();
    const int tb = ctrl[1];

    #pragma unroll
    for (int k = 0; k < KPT; k++) {
        int bk = rbk[k];
        if (bk >= tb) {
            int idx = tid + k * TPB;
            int pos = atomicAdd(&ctrl[0], 1);
            if (pos < BANDCAP)
                band[pos] = ((u64)mono(rs[k]) << 32) | (u64)(0xFFFFFFFFu - (u32)idx);
        }
    }
    __syncthreads();
    const int L = min(ctrl[0], BANDCAP);
    if (tid == 0) g_len[b] = L;

    int P = 1; while (P < L) P <<= 1; if (P < 2) P = 2;
    for (int i = L + tid; i < P; i += TPB) band[i] = 0ull;
    __syncthreads();

    for (int ksz = 2; ksz <= P; ksz <<= 1) {
        for (int j = ksz >> 1; j > 0; j >>= 1) {
            for (int t = tid; t < P; t += TPB) {
                int p = t ^ j;
                if (p > t) {
                    u64 a = band[t], c = band[p];
                    bool descBlock = ((t & ksz) == 0);
                    if (descBlock ? (a < c) : (a > c)) { band[t] = c; band[p] = a; }
                }
            }
            __syncthreads();
        }
    }

    for (int i = tid; i < L; i += TPB) g_keys[b * SORTCAP + i] = band[i];
    const int C = min(L, CHUNK);
    if (tid < C) {
        u64 key = band[tid];
        int oi = (int)(0xFFFFFFFFu - (u32)(key & 0xFFFFFFFFull));
        float4 bv = *(const float4*)(bb + (size_t)oi * 4);
        g_cbox[b * CHUNK + tid] = bv;
        g_carA[b * CHUNK + tid] = (bv.z - bv.x) * (bv.w - bv.y);
        g_cmsk[b * CHUNK + tid] = cellmask(bv);
    }
}

// =======================================================================
// K2: suppression matrix for chunk0, 2 CTAs per image (alternating 32-row
//     chunks), cell-mask prefilter, transposed coalesced writes
// =======================================================================
__global__ __launch_bounds__(256, 1)
void k2_matrix()
{
    __shared__ float4 scb[CHUNK];
    __shared__ float  sar[CHUNK];
    __shared__ u32    scm[CHUNK];

    const int img = blockIdx.y, g = blockIdx.x;
    const int tid = threadIdx.x, lane = tid & 31, w = tid >> 5;
    const int C = min(g_len[img], CHUNK);

    for (int i = tid; i < CHUNK; i += 256) {
        scb[i] = g_cbox[img * CHUNK + i];
        sar[i] = g_carA[img * CHUNK + i];
        scm[i] = g_cmsk[img * CHUNK + i];
    }
    __syncthreads();

    const int i = 32 * (2 * w + g) + lane;     // chunk c=2w+g, rows 32c..32c+31
    u64* mrow = g_mat + (size_t)img * (MASKW * CHUNK);

    if (i < C) {
        const float4 bv = scb[i];
        const float  ar = sar[i];
        const u32    mycm = scm[i];
        u64 acc = 0ull;
        for (int j = 0; j < i; j++) {
            u32 vm = scm[j] & mycm;
            if ((vm & 0xFFFFu) != 0u && (vm >> 16) != 0u) {
                float4 bj = scb[j];
                float aj = sar[j];
                float ix = fminf(bv.z, bj.z) - fmaxf(bv.x, bj.x);
                float iy = fminf(bv.w, bj.w) - fmaxf(bv.y, bj.y);
                if (ix > 0.f && iy > 0.f) {
                    float inter = ix * iy;
                    float denom = aj + ar - inter + 1e-7f;
                    float diff  = __fmaf_rn(-IOU_T, denom, inter);
                    bool s;
                    if (fabsf(diff) > 1e-4f * denom) s = (diff > 0.f);
                    else s = sup_exact(ix, iy, aj, ar);
                    if (s) acc |= 1ull << (j & 63);
                }
            }
            if ((j & 63) == 63) { mrow[(j >> 6) * CHUNK + i] = acc; acc = 0ull; }
        }
        if (i & 63) mrow[(i >> 6) * CHUNK + i] = acc;
        for (int ww = (i + 63) >> 6; ww < MASKW; ww++) mrow[ww * CHUNK + i] = 0ull;
    } else if (i < CHUNK) {
        #pragma unroll
        for (int ww = 0; ww < MASKW; ww++) mrow[ww * CHUNK + i] = 0ull;
    }
}

// =======================================================================
// K3: fixpoint + append + outputs; full exact fallback (round-3 machinery)
// =======================================================================
struct Sm {
    u64* band; u64* maskT; u64* keptw;
    float4* cb4; float* car; float* csc; int* cidx;
    u32* sfx; u32* blocksum; u32* wball; u32* wchg;
    float *kx1, *ky1, *kx2, *ky2, *kar;
    int* selIdx; float* selScore; int* ctrl;
};

// Block-wide fixpoint + ranked append for the current chunk's per-thread
// candidate (bv, ar, sc, oi, init). Returns new kept count (uniform).
__device__ __forceinline__ int fixpoint_append(const Sm& s, int tid, int lane, int wid,
                                               bool init, float4 bv, float ar, float sc, int oi,
                                               int kept0)
{
    u32 m = __ballot_sync(0xFFFFFFFFu, init);
    if (lane == 0) s.wball[wid] = m;
    __syncthreads();
    if (tid < MASKW)
        s.keptw[tid] = (u64)s.wball[2 * tid] | ((u64)s.wball[2 * tid + 1] << 32);
    __syncthreads();

    for (int iter = 0; iter < CHUNK; iter++) {
        u64 any = 0ull;
        #pragma unroll
        for (int w = 0; w < MASKW; w++)
            any |= s.maskT[w * CHUNK + tid] & s.keptw[w];
        bool nb = init && (any == 0ull);
        u32 mm = __ballot_sync(0xFFFFFFFFu, nb);
        if (lane == 0) s.wball[wid] = mm;
        __syncthreads();
        if (tid < MASKW) {
            u64 nw = (u64)s.wball[2 * tid] | ((u64)s.wball[2 * tid + 1] << 32);
            u32 ch = 0u;
            if (nw != s.keptw[tid]) { s.keptw[tid] = nw; ch = 1u; }
            s.wchg[tid] = ch;
        }
        __syncthreads();
        u32 c = 0;
        #pragma unroll
        for (int w = 0; w < MASKW; w++) c |= s.wchg[w];
        if (c == 0u) break;
    }

    int totalK = 0;
    #pragma unroll
    for (int w = 0; w < MASKW; w++) totalK += __popcll(s.keptw[w]);
    int take = min(totalK, MAXDET - kept0);

    bool mine = (s.keptw[tid >> 6] >> (tid & 63)) & 1ull;
    if (mine) {
        int rank = 0;
        int wi = tid >> 6;
        #pragma unroll
        for (int w = 0; w < MASKW; w++) if (w < wi) rank += __popcll(s.keptw[w]);
        rank += __popcll(s.keptw[wi] & ((1ull << (tid & 63)) - 1ull));
        if (rank < take) {
            int pos = kept0 + rank;
            s.kx1[pos] = bv.x; s.ky1[pos] = bv.y;
            s.kx2[pos] = bv.z; s.ky2[pos] = bv.w;
            s.kar[pos] = ar;
            s.selIdx[pos] = oi; s.selScore[pos] = sc;
        }
    }
    if (tid == 0) s.ctrl[1] = kept0 + take;
    __syncthreads();
    return s.ctrl[1];
}

// Full chunk processing (inline matrix build) — exact round-3 path for
// fallback chunks. Block-wide; returns new kept count.
__device__ int process_chunk_full(const float* bb, const Sm& s,
                                  int tid, int lane, int wid, int cs, int L)
{
    const int kept0 = s.ctrl[1];
    const int ci = cs + tid;
    const bool valid = (ci < L);

    float4 bv = make_float4(0.f, 0.f, 0.f, 0.f);
    float sc = 0.f; int oi = 0;
    if (valid) {
        u64 key = s.band[ci];
        oi = (int)(0xFFFFFFFFu - (u32)(key & 0xFFFFFFFFull));
        sc = __uint_as_float(((u32)(key >> 32)) ^ 0x80000000u);
        bv = *(const float4*)(bb + (size_t)oi * 4);
    }
    float ar = (bv.z - bv.x) * (bv.w - bv.y);

    bool init = valid;
    for (int k = 0; k < kept0 && init; k++) {
        float ix = fminf(bv.z, s.kx2[k]) - fmaxf(bv.x, s.kx1[k]);
        float iy = fminf(bv.w, s.ky2[k]) - fmaxf(bv.y, s.ky1[k]);
        if (sup_exact(ix, iy, s.kar[k], ar)) init = false;
    }

    s.cb4[tid] = bv; s.car[tid] = ar;
    __syncthreads();

    {
        const int i = tid;
        u64 acc = 0ull;
        for (int j = 0; j < i; j++) {
            float4 bj = s.cb4[j];
            float aj = s.car[j];
            float ix = fminf(bv.z, bj.z) - fmaxf(bv.x, bj.x);
            float iy = fminf(bv.w, bj.w) - fmaxf(bv.y, bj.y);
            if (ix > 0.f && iy > 0.f) {
                float inter = ix * iy;
                float denom = aj + ar - inter + 1e-7f;
                float diff  = __fmaf_rn(-IOU_T, denom, inter);
                bool sp;
                if (fabsf(diff) > 1e-4f * denom) sp = (diff > 0.f);
                else sp = sup_exact(ix, iy, aj, ar);
                if (sp) acc |= 1ull << (j & 63);
            }
            if ((j & 63) == 63) { s.maskT[(j >> 6) * CHUNK + i] = acc; acc = 0ull; }
        }
        if (i & 63) s.maskT[(i >> 6) * CHUNK + i] = acc;
        for (int w = (i + 63) >> 6; w < MASKW; w++) s.maskT[w * CHUNK + i] = 0ull;
    }
    __syncthreads();

    return fixpoint_append(s, tid, lane, wid, init, bv, ar, sc, oi, kept0);
}

__global__ __launch_bounds__(TPB, 1)
void k3_nms(const float* __restrict__ boxes, const float* __restrict__ scores,
            const float* __restrict__ kpts, float* __restrict__ out)
{
    extern __shared__ unsigned char smraw[];
    Sm s;
    s.band  = (u64*)smraw;                        // [SORTCAP]
    s.maskT = s.band + SORTCAP;                   // [MASKW*CHUNK]
    s.keptw = s.maskT + MASKW * CHUNK;            // [8]
    s.cb4   = (float4*)(s.keptw + 8);             // [CHUNK]
    s.car   = (float*)(s.cb4 + CHUNK);            // [CHUNK]
    s.csc   = s.car + CHUNK;                      // [CHUNK] (unused, layout keep)
    s.cidx  = (int*)(s.csc + CHUNK);              // [CHUNK] (unused)
    s.sfx   = (u32*)(s.cidx + CHUNK);             // [NBUCK]
    s.blocksum = s.sfx + NBUCK;                   // [16]
    s.wball    = s.blocksum + 16;                 // [16]
    s.wchg     = s.wball + 16;                    // [8]
    s.kx1 = (float*)(s.wchg + 8);
    s.ky1 = s.kx1 + MAXDET; s.kx2 = s.ky1 + MAXDET;
    s.ky2 = s.kx2 + MAXDET; s.kar = s.ky2 + MAXDET;
    s.selIdx   = (int*)(s.kar + MAXDET);
    s.selScore = (float*)(s.selIdx + MAXDET);
    s.ctrl     = (int*)(s.selScore + MAXDET);

    const int b = blockIdx.x, tid = threadIdx.x, lane = tid & 31, wid = tid >> 5;
    const float* bb = boxes  + (size_t)b * NANCH * 4;
    const float* ss = scores + (size_t)b * NANCH;

    const int L = g_len[b];
    const int C = min(L, CHUNK);
    if (tid == 0) s.ctrl[1] = 0;

    // load sorted keys + precomputed chunk0 data + matrix
    for (int i = tid; i < L; i += TPB) s.band[i] = g_keys[b * SORTCAP + i];
    #pragma unroll
    for (int w = 0; w < MASKW; w++)
        s.maskT[w * CHUNK + tid] = g_mat[(size_t)b * (MASKW * CHUNK) + w * CHUNK + tid];

    float4 bv = make_float4(0.f, 0.f, 0.f, 0.f);
    float ar = 0.f, sc = 0.f; int oi = 0;
    bool init = (tid < C);
    if (init) {
        bv = g_cbox[b * CHUNK + tid];
        ar = g_carA[b * CHUNK + tid];
        u64 key;
        __syncthreads();     // band[] ready (also covers ctrl init)
        key = s.band[tid];
        oi = (int)(0xFFFFFFFFu - (u32)(key & 0xFFFFFFFFull));
        sc = __uint_as_float(((u32)(key >> 32)) ^ 0x80000000u);
    } else {
        __syncthreads();
    }

    int kept = fixpoint_append(s, tid, lane, wid, init, bv, ar, sc, oi, 0);

    // ---------------- exact fallback (statistically never taken) ----------
    if (kept < MAXDET) {
        // remaining chunks of band 0
        for (int cs = CHUNK; cs < L && kept < MAXDET; cs += CHUNK)
            kept = process_chunk_full(bb, s, tid, lane, wid, cs, L);

        if (kept < MAXDET) {
            // lazy histogram + suffix scan
            float rs[KPT]; int rbk[KPT];
            for (int i = tid; i < NBUCK; i += TPB) s.sfx[i] = 0u;
            __syncthreads();
            #pragma unroll
            for (int k = 0; k < KPT; k++) {
                int idx = tid + k * TPB;
                float sv = (idx < NANCH) ? ss[idx] : 0.0f;
                rs[k] = sv; int bk = -1;
                if (idx < NANCH && sv > SCORE_T) {
                    bk = min((int)(sv * (float)NBUCK), NBUCK - 1);
                    atomicAdd(&s.sfx[bk], 1u);
                }
                rbk[k] = bk;
            }
            __syncthreads();
            {
                u32 lsum[8]; u32 run = 0;
                const int base = tid * 8;
                #pragma unroll
                for (int j = 7; j >= 0; j--) { run += s.sfx[base + j]; lsum[j] = run; }
                u32 x = run;
                #pragma unroll
                for (int off = 1; off < 32; off <<= 1) {
                    u32 o = __shfl_down_sync(0xFFFFFFFFu, x, off);
                    if (lane + off < 32) x += o;
                }
                if (lane == 0) s.blocksum[wid] = x;
                __syncthreads();
                u32 woff = 0;
                for (int w = wid + 1; w < TPB / 32; w++) woff += s.blocksum[w];
                u32 excl = woff + (x - run);
                #pragma unroll
                for (int j = 0; j < 8; j++) s.sfx[base + j] = excl + lsum[j];
                __syncthreads();
            }

            int curTop = g_tbnd[b];
            while (kept < MAXDET) {
                u32 proc  = (curTop < NBUCK) ? s.sfx[curTop] : 0u;
                u32 total = s.sfx[0];
                u32 remaining = total - proc;
                if (remaining == 0u) break;

                if (tid == 0) {
                    u32 want = remaining < (u32)KWANT ? remaining : (u32)KWANT;
                    u32 target = proc + want;
                    int tb = 0;
                    {
                        int lo = 0, hi = curTop - 1;
                        while (lo <= hi) {
                            int mid = (lo + hi) >> 1;
                            if (s.sfx[mid] >= target) { tb = mid; lo = mid + 1; }
                            else hi = mid - 1;
                        }
                    }
                    if (s.sfx[tb] - proc > (u32)BANDCAP) {
                        u32 t2 = proc + BANDCAP;
                        int lo = tb + 1, hi = curTop - 1, nb2 = curTop - 1;
                        while (lo <= hi) {
                            int mid = (lo + hi) >> 1;
                            if (s.sfx[mid] <= t2) { nb2 = mid; hi = mid - 1; }
                            else lo = mid + 1;
                        }
                        tb = nb2;
                    }
                    s.ctrl[3] = tb; s.ctrl[0] = 0;
                }
                __syncthreads();
                const int tb = s.ctrl[3];

                #pragma unroll
                for (int k = 0; k < KPT; k++) {
                    int bk = rbk[k];
                    if (bk >= tb && bk < curTop) {
                        int idx = tid + k * TPB;
                        int pos = atomicAdd(&s.ctrl[0], 1);
                        if (pos < BANDCAP)
                            s.band[pos] = ((u64)mono(rs[k]) << 32) |
                                          (u64)(0xFFFFFFFFu - (u32)idx);
                    }
                }
                __syncthreads();
                int Lb = min(s.ctrl[0], BANDCAP);

                int P = 1; while (P < Lb) P <<= 1; if (P < 2) P = 2;
                for (int i = Lb + tid; i < P; i += TPB) s.band[i] = 0ull;
                __syncthreads();
                for (int ksz = 2; ksz <= P; ksz <<= 1) {
                    for (int j = ksz >> 1; j > 0; j >>= 1) {
                        for (int t = tid; t < P; t += TPB) {
                            int p = t ^ j;
                            if (p > t) {
                                u64 a = s.band[t], c = s.band[p];
                                bool descBlock = ((t & ksz) == 0);
                                if (descBlock ? (a < c) : (a > c)) { s.band[t] = c; s.band[p] = a; }
                            }
                        }
                        __syncthreads();
                    }
                }

                for (int cs = 0; cs < Lb && kept < MAXDET; cs += CHUNK)
                    kept = process_chunk_full(bb, s, tid, lane, wid, cs, Lb);

                curTop = tb;
                __syncthreads();
            }
        }
    }
    __syncthreads();
    const int nsel = s.ctrl[1];

    // ---------------- outputs ----------------
    float* out_b = out + (size_t)b * MAXDET * 4;
    float* out_s = out + (size_t)NBATCH * MAXDET * 4 + (size_t)b * MAXDET;
    float* out_l = out + (size_t)NBATCH * MAXDET * 5 + (size_t)b * MAXDET;
    float* out_k = out + (size_t)NBATCH * MAXDET * 6 + (size_t)b * MAXDET * KD;
    const float* kb = kpts + (size_t)b * NANCH * KD;

    for (int t = tid; t < MAXDET; t += TPB) {
        float4 obv = make_float4(0.f, 0.f, 0.f, 0.f);
        float osc = 0.f;
        if (t < nsel) {
            int idx = s.selIdx[t];
            obv = *(const float4*)(bb + (size_t)idx * 4);
            osc = s.selScore[t];
        }
        *(float4*)(out_b + (size_t)t * 4) = obv;
        out_s[t] = osc;
        out_l[t] = 0.0f;
    }
    for (int j = tid; j < MAXDET * KD; j += TPB) {
        int t = j / KD;
        int c = j - t * KD;
        int idx = (t < nsel) ? s.selIdx[t] : 0;
        out_k[j] = kb[(size_t)idx * KD + c];
    }
}

extern "C" void kernel_launch(void* const* d_in, const int* in_sizes, int n_in,
                              void* d_out, int out_size) {
    const float* boxes  = (const float*)d_in[0];
    const float* scores = (const float*)d_in[1];
    const float* kpts   = (const float*)d_in[2];
    float* out = (float*)d_out;

    const int smem1 = SORTCAP * 8 + NBUCK * 4 + 16 * 4 + 8 * 4;
    const int smem3 = SORTCAP * 8                  // band
                    + MASKW * CHUNK * 8            // maskT
                    + 8 * 8                        // keptw
                    + CHUNK * 16                   // cb4
                    + CHUNK * 4 * 3                // car,csc,cidx
                    + NBUCK * 4                    // sfx
                    + 16 * 4 + 16 * 4 + 8 * 4      // blocksum, wball, wchg
                    + 5 * MAXDET * 4               // kept boxes
                    + MAXDET * 4 + MAXDET * 4      // selIdx + selScore
                    + 8 * 4;                       // ctrl

    cudaFuncSetAttribute(k1_select, cudaFuncAttributeMaxDynamicSharedMemorySize, smem1);
    cudaFuncSetAttribute(k3_nms,    cudaFuncAttributeMaxDynamicSharedMemorySize, smem3);

    k1_select<<<NBATCH, TPB, smem1>>>(boxes, scores);
    dim3 g2(2, NBATCH);
    k2_matrix<<<g2, 256>>>();
    k3_nms<<<NBATCH, TPB, smem3>>>(boxes, scores, kpts, out);
}

// round 5
// speedup vs baseline: 1.9412x; 1.9412x over previous
#include <cuda_runtime.h>

#define NBATCH 64
#define NANCH  8400
#define KD     51
#define MAXDET 300
#define TPB    512
#define KPT    ((NANCH + TPB - 1) / TPB)   // 17

#define NBUCK   4096
#define KWANT   480
#define FASTCAP 512
#define BANDCAP 1536
#define CHUNK   512
#define MASKW   8

#define SCORE_T 0.001f
#define IOU_T   0.7f

typedef unsigned long long u64;
typedef unsigned int u32;

__device__ __forceinline__ u32 mono(float s) {
    u32 u = __float_as_uint(s);
    return (u & 0x80000000u) ? ~u : (u | 0x80000000u);
}

__device__ __forceinline__ bool sup_exact(float ix, float iy, float a_sel, float a_cand) {
    float inter = fmaxf(ix, 0.0f) * fmaxf(iy, 0.0f);
    float iou = inter / (a_sel + a_cand - inter + 1e-7f);
    return iou > IOU_T;
}

// Branchless main-path pair test; exact reference-form fallback only near the
// decision boundary (same scheme as rounds 1-4, rel_err 0.0).
__device__ __forceinline__ bool pairtest(float4 bj, float aj,
                                         float bx, float by, float bz, float bw, float ar) {
    float ix = fminf(bz, bj.z) - fmaxf(bx, bj.x);
    float iy = fminf(bw, bj.w) - fmaxf(by, bj.y);
    float inter = fmaxf(ix, 0.0f) * fmaxf(iy, 0.0f);
    float denom = aj + ar - inter + 1e-7f;
    float diff  = __fmaf_rn(-IOU_T, denom, inter);     // inter - 0.7*denom
    bool sup;
    if (fabsf(diff) > 1e-4f * denom) sup = (diff > 0.0f);
    else                             sup = sup_exact(ix, iy, aj, ar);
    return sup;
}

struct Sm {
    u64* band; u64* maskT; u64* keptw;
    float4* cb4; float* car;
    u32* sfx; u32* blocksum; u32* wball; u32* wchg;
    float *kx1, *ky1, *kx2, *ky2, *kar;
    int* selIdx; float* selScore; int* ctrl;
};

// Block-wide fixpoint + ranked append. Returns new kept count (uniform).
__device__ __forceinline__ int fixpoint_append(const Sm& s, int tid, int lane, int wid,
                                               bool init, float4 bv, float ar, float sc, int oi,
                                               int kept0)
{
    u32 m = __ballot_sync(0xFFFFFFFFu, init);
    if (lane == 0) s.wball[wid] = m;
    __syncthreads();
    if (tid < MASKW)
        s.keptw[tid] = (u64)s.wball[2 * tid] | ((u64)s.wball[2 * tid + 1] << 32);
    __syncthreads();

    for (int iter = 0; iter < CHUNK; iter++) {
        u64 any = 0ull;
        #pragma unroll
        for (int w = 0; w < MASKW; w++)
            any |= s.maskT[w * CHUNK + tid] & s.keptw[w];
        bool nb = init && (any == 0ull);
        u32 mm = __ballot_sync(0xFFFFFFFFu, nb);
        if (lane == 0) s.wball[wid] = mm;
        __syncthreads();
        if (tid < MASKW) {
            u64 nw = (u64)s.wball[2 * tid] | ((u64)s.wball[2 * tid + 1] << 32);
            u32 ch = 0u;
            if (nw != s.keptw[tid]) { s.keptw[tid] = nw; ch = 1u; }
            s.wchg[tid] = ch;
        }
        __syncthreads();
        u32 c = 0;
        #pragma unroll
        for (int w = 0; w < MASKW; w++) c |= s.wchg[w];
        if (c == 0u) break;
    }

    int totalK = 0;
    #pragma unroll
    for (int w = 0; w < MASKW; w++) totalK += __popcll(s.keptw[w]);
    int take = min(totalK, MAXDET - kept0);

    bool mine = (s.keptw[tid >> 6] >> (tid & 63)) & 1ull;
    if (mine) {
        int rank = 0;
        int wi = tid >> 6;
        #pragma unroll
        for (int w = 0; w < MASKW; w++) if (w < wi) rank += __popcll(s.keptw[w]);
        rank += __popcll(s.keptw[wi] & ((1ull << (tid & 63)) - 1ull));
        if (rank < take) {
            int pos = kept0 + rank;
            s.kx1[pos] = bv.x; s.ky1[pos] = bv.y;
            s.kx2[pos] = bv.z; s.ky2[pos] = bv.w;
            s.kar[pos] = ar;
            s.selIdx[pos] = oi; s.selScore[pos] = sc;
        }
    }
    if (tid == 0) s.ctrl[1] = kept0 + take;
    __syncthreads();
    return s.ctrl[1];
}

// Unrolled suppression matrix build for the per-thread row i.
// cb4/car must be valid for [0, C); rows >= C just zero their words.
__device__ __forceinline__ void build_matrix_row(const Sm& s, int tid, int C,
                                                 float4 bv, float ar)
{
    const int i = tid;
    if (i < C) {
        const float bx = bv.x, by = bv.y, bz = bv.z, bw = bv.w;
        u64 acc = 0ull;
        int j = 0;
        for (; j + 4 <= i; j += 4) {
            float4 b0 = s.cb4[j],     b1 = s.cb4[j + 1];
            float4 b2 = s.cb4[j + 2], b3 = s.cb4[j + 3];
            float a0 = s.car[j],     a1 = s.car[j + 1];
            float a2 = s.car[j + 2], a3 = s.car[j + 3];
            u32 nib = 0;
            if (pairtest(b0, a0, bx, by, bz, bw, ar)) nib |= 1u;
            if (pairtest(b1, a1, bx, by, bz, bw, ar)) nib |= 2u;
            if (pairtest(b2, a2, bx, by, bz, bw, ar)) nib |= 4u;
            if (pairtest(b3, a3, bx, by, bz, bw, ar)) nib |= 8u;
            acc |= (u64)nib << (j & 63);
            if (((j + 4) & 63) == 0) { s.maskT[(j >> 6) * CHUNK + i] = acc; acc = 0ull; }
        }
        for (; j < i; j++) {
            if (pairtest(s.cb4[j], s.car[j], bx, by, bz, bw, ar))
                acc |= 1ull << (j & 63);
        }
        if (i & 63) s.maskT[(i >> 6) * CHUNK + i] = acc;
        for (int w = (i + 63) >> 6; w < MASKW; w++) s.maskT[w * CHUNK + i] = 0ull;
    } else {
        #pragma unroll
        for (int w = 0; w < MASKW; w++) s.maskT[w * CHUNK + i] = 0ull;
    }
}

// Generic exact fallback chunk (round-3 machinery; cold path).
__device__ int process_chunk_full(const float* bb, const Sm& s,
                                  int tid, int lane, int wid, int cs, int L)
{
    const int kept0 = s.ctrl[1];
    const int ci = cs + tid;
    const bool valid = (ci < L);

    float4 bv = make_float4(0.f, 0.f, 0.f, 0.f);
    float sc = 0.f; int oi = 0;
    if (valid) {
        u64 key = s.band[ci];
        oi = (int)(0xFFFFFFFFu - (u32)(key & 0xFFFFFFFFull));
        sc = __uint_as_float(((u32)(key >> 32)) ^ 0x80000000u);
        bv = *(const float4*)(bb + (size_t)oi * 4);
    }
    float ar = (bv.z - bv.x) * (bv.w - bv.y);

    bool init = valid;
    for (int k = 0; k < kept0 && init; k++) {
        float ix = fminf(bv.z, s.kx2[k]) - fmaxf(bv.x, s.kx1[k]);
        float iy = fminf(bv.w, s.ky2[k]) - fmaxf(bv.y, s.ky1[k]);
        if (sup_exact(ix, iy, s.kar[k], ar)) init = false;
    }

    s.cb4[tid] = bv; s.car[tid] = ar;
    __syncthreads();

    int C = min(L - cs, CHUNK);
    build_matrix_row(s, tid, C, bv, ar);
    __syncthreads();

    return fixpoint_append(s, tid, lane, wid, init, bv, ar, sc, oi, kept0);
}

__global__ __launch_bounds__(TPB, 1)
void nms_pose_kernel(const float* __restrict__ boxes, const float* __restrict__ scores,
                     const float* __restrict__ kpts, float* __restrict__ out)
{
    extern __shared__ unsigned char smraw[];
    Sm s;
    s.band  = (u64*)smraw;                        // [BANDCAP]
    s.maskT = s.band + BANDCAP;                   // [MASKW*CHUNK]
    s.keptw = s.maskT + MASKW * CHUNK;            // [8]
    s.cb4   = (float4*)(s.keptw + 8);             // [CHUNK]
    s.car   = (float*)(s.cb4 + CHUNK);            // [CHUNK]
    s.sfx   = (u32*)(s.car + CHUNK);              // [NBUCK]
    s.blocksum = s.sfx + NBUCK;                   // [16]
    s.wball    = s.blocksum + 16;                 // [16]
    s.wchg     = s.wball + 16;                    // [8]
    s.kx1 = (float*)(s.wchg + 8);
    s.ky1 = s.kx1 + MAXDET; s.kx2 = s.ky1 + MAXDET;
    s.ky2 = s.kx2 + MAXDET; s.kar = s.ky2 + MAXDET;
    s.selIdx   = (int*)(s.kar + MAXDET);
    s.selScore = (float*)(s.selIdx + MAXDET);
    s.ctrl     = (int*)(s.selScore + MAXDET);     // [0]=cnt [1]=kept [2]=fastok [3]=tb

    const int b = blockIdx.x, tid = threadIdx.x, lane = tid & 31, wid = tid >> 5;
    const float* bb = boxes  + (size_t)b * NANCH * 4;
    const float* ss = scores + (size_t)b * NANCH;

    // ---------- Phase A: histogram ----------
    for (int i = tid; i < NBUCK; i += TPB) s.sfx[i] = 0u;
    if (tid == 0) s.ctrl[1] = 0;
    __syncthreads();

    {
        float rs[KPT]; int rbk[KPT];
        #pragma unroll
        for (int k = 0; k < KPT; k++) {
            int idx = tid + k * TPB;
            float sv = (idx < NANCH) ? ss[idx] : 0.0f;
            rs[k] = sv; int bk = -1;
            if (idx < NANCH && sv > SCORE_T) {
                bk = min((int)(sv * (float)NBUCK), NBUCK - 1);
                atomicAdd(&s.sfx[bk], 1u);
            }
            rbk[k] = bk;
        }
        __syncthreads();

        // ---------- Phase B: suffix sums ----------
        {
            u32 lsum[8]; u32 run = 0;
            const int base = tid * 8;                 // NBUCK == TPB*8
            #pragma unroll
            for (int j = 7; j >= 0; j--) { run += s.sfx[base + j]; lsum[j] = run; }
            u32 x = run;
            #pragma unroll
            for (int off = 1; off < 32; off <<= 1) {
                u32 o = __shfl_down_sync(0xFFFFFFFFu, x, off);
                if (lane + off < 32) x += o;
            }
            if (lane == 0) s.blocksum[wid] = x;
            __syncthreads();
            u32 woff = 0;
            for (int w = wid + 1; w < TPB / 32; w++) woff += s.blocksum[w];
            u32 excl = woff + (x - run);
            #pragma unroll
            for (int j = 0; j < 8; j++) s.sfx[base + j] = excl + lsum[j];
            __syncthreads();
        }

        // ---------- Phase C: pick fast band [tb, NBUCK), count <= 512 ----------
        if (tid == 0) {
            u32 total = s.sfx[0];
            int fastok = 0, tb = NBUCK;
            if (total > 0u) {
                u32 want = total < (u32)KWANT ? total : (u32)KWANT;
                int lo = 0, hi = NBUCK - 1; tb = 0;
                while (lo <= hi) {
                    int m = (lo + hi) >> 1;
                    if (s.sfx[m] >= want) { tb = m; lo = m + 1; } else hi = m - 1;
                }
                if (s.sfx[tb] > (u32)FASTCAP) {
                    // smallest index with sfx <= FASTCAP (sfx non-increasing)
                    int lo2 = tb + 1, hi2 = NBUCK - 1, nb = NBUCK;
                    while (lo2 <= hi2) {
                        int m = (lo2 + hi2) >> 1;
                        if (s.sfx[m] <= (u32)FASTCAP) { nb = m; hi2 = m - 1; }
                        else lo2 = m + 1;
                    }
                    tb = nb;
                }
                if (tb < NBUCK && s.sfx[tb] > 0u && s.sfx[tb] <= (u32)FASTCAP) fastok = 1;
            }
            s.ctrl[0] = 0; s.ctrl[2] = fastok; s.ctrl[3] = tb;
        }
        __syncthreads();
        const int fastok = s.ctrl[2];
        const int tb = s.ctrl[3];

        // ---------- Phase D: fast gather ----------
        if (fastok) {
            #pragma unroll
            for (int k = 0; k < KPT; k++) {
                if (rbk[k] >= tb) {
                    int idx = tid + k * TPB;
                    int pos = atomicAdd(&s.ctrl[0], 1);
                    if (pos < FASTCAP)
                        s.band[pos] = ((u64)mono(rs[k]) << 32) |
                                      (u64)(0xFFFFFFFFu - (u32)idx);
                }
            }
        }
        __syncthreads();
    }   // rs/rbk dead here

    int kept = 0;
    const int fastok = s.ctrl[2];
    const int tb = s.ctrl[3];

    if (fastok) {
        const int L = min(s.ctrl[0], FASTCAP);
        if (tid >= L) s.band[tid] = 0ull;      // pad (sorts to tail)
        __syncthreads();

        // ---------- Phase E: register bitonic sort (descending), P = 512 ----------
        u64 v = s.band[tid];
        // intra-warp levels k=2..32 (35 total shfl passes incl. later tails)
        #pragma unroll
        for (int k = 2; k <= 32; k <<= 1) {
            #pragma unroll
            for (int j = k >> 1; j > 0; j >>= 1) {
                u64 o = __shfl_xor_sync(0xFFFFFFFFu, v, j);
                bool lower = (tid & j) == 0;
                bool desc  = (tid & k) == 0;
                bool takeMax = (desc == lower);
                v = takeMax ? (v > o ? v : o) : (v > o ? o : v);
            }
        }
        // levels k=64..512: strides >=32 via smem, <=16 via shfl
        #pragma unroll
        for (int k = 64; k <= 512; k <<= 1) {
            for (int j = k >> 1; j >= 32; j >>= 1) {
                s.band[tid] = v;
                __syncthreads();
                u64 o = s.band[tid ^ j];
                __syncthreads();
                bool lower = (tid & j) == 0;
                bool desc  = (tid & k) == 0;
                bool takeMax = (desc == lower);
                v = takeMax ? (v > o ? v : o) : (v > o ? o : v);
            }
            #pragma unroll
            for (int j = 16; j > 0; j >>= 1) {
                u64 o = __shfl_xor_sync(0xFFFFFFFFu, v, j);
                bool lower = (tid & j) == 0;
                bool desc  = (tid & k) == 0;
                bool takeMax = (desc == lower);
                v = takeMax ? (v > o ? v : o) : (v > o ? o : v);
            }
        }

        // ---------- Phase F: decode, matrix, fixpoint ----------
        const bool valid = (tid < L);
        float4 bv = make_float4(0.f, 0.f, 0.f, 0.f);
        float sc = 0.f; int oi = 0;
        if (valid) {
            oi = (int)(0xFFFFFFFFu - (u32)(v & 0xFFFFFFFFull));
            sc = __uint_as_float(((u32)(v >> 32)) ^ 0x80000000u);
            bv = *(const float4*)(bb + (size_t)oi * 4);
        }
        float ar = (bv.z - bv.x) * (bv.w - bv.y);
        s.cb4[tid] = bv; s.car[tid] = ar;
        __syncthreads();

        build_matrix_row(s, tid, L, bv, ar);
        __syncthreads();

        kept = fixpoint_append(s, tid, lane, wid, valid, bv, ar, sc, oi, 0);
    }

    // ---------- Phase G: exact generic fallback (cold) ----------
    if (kept < MAXDET) {
        int curTop = fastok ? tb : NBUCK;
        while (kept < MAXDET) {
            u32 proc  = (curTop < NBUCK) ? s.sfx[curTop] : 0u;
            u32 total = s.sfx[0];
            u32 remaining = total - proc;
            if (remaining == 0u) break;

            if (tid == 0) {
                u32 want = remaining < (u32)FASTCAP ? remaining : (u32)FASTCAP;
                u32 target = proc + want;
                int tb2 = 0;
                {
                    int lo = 0, hi = curTop - 1;
                    while (lo <= hi) {
                        int mid = (lo + hi) >> 1;
                        if (s.sfx[mid] >= target) { tb2 = mid; lo = mid + 1; }
                        else hi = mid - 1;
                    }
                }
                if (s.sfx[tb2] - proc > (u32)BANDCAP) {
                    u32 t2 = proc + BANDCAP;
                    int lo = tb2 + 1, hi = curTop - 1, nb2 = curTop - 1;
                    while (lo <= hi) {
                        int mid = (lo + hi) >> 1;
                        if (s.sfx[mid] <= t2) { nb2 = mid; hi = mid - 1; }
                        else lo = mid + 1;
                    }
                    tb2 = nb2;
                }
                s.ctrl[3] = tb2; s.ctrl[0] = 0;
            }
            __syncthreads();
            const int tb2 = s.ctrl[3];

            #pragma unroll
            for (int k = 0; k < KPT; k++) {
                int idx = tid + k * TPB;
                if (idx < NANCH) {
                    float sv = ss[idx];
                    if (sv > SCORE_T) {
                        int bk = min((int)(sv * (float)NBUCK), NBUCK - 1);
                        if (bk >= tb2 && bk < curTop) {
                            int pos = atomicAdd(&s.ctrl[0], 1);
                            if (pos < BANDCAP)
                                s.band[pos] = ((u64)mono(sv) << 32) |
                                              (u64)(0xFFFFFFFFu - (u32)idx);
                        }
                    }
                }
            }
            __syncthreads();
            int Lb = min(s.ctrl[0], BANDCAP);

            int P = 1; while (P < Lb) P <<= 1; if (P < 2) P = 2;
            for (int i = Lb + tid; i < P; i += TPB) s.band[i] = 0ull;
            __syncthreads();
            for (int ksz = 2; ksz <= P; ksz <<= 1) {
                for (int j = ksz >> 1; j > 0; j >>= 1) {
                    for (int t = tid; t < P; t += TPB) {
                        int p = t ^ j;
                        if (p > t) {
                            u64 a = s.band[t], c = s.band[p];
                            bool descBlock = ((t & ksz) == 0);
                            if (descBlock ? (a < c) : (a > c)) { s.band[t] = c; s.band[p] = a; }
                        }
                    }
                    __syncthreads();
                }
            }

            for (int cs = 0; cs < Lb && kept < MAXDET; cs += CHUNK)
                kept = process_chunk_full(bb, s, tid, lane, wid, cs, Lb);

            curTop = tb2;
            __syncthreads();
        }
    }
    __syncthreads();
    const int nsel = s.ctrl[1];

    // ---------- Phase H: outputs ----------
    float* out_b = out + (size_t)b * MAXDET * 4;
    float* out_s = out + (size_t)NBATCH * MAXDET * 4 + (size_t)b * MAXDET;
    float* out_l = out + (size_t)NBATCH * MAXDET * 5 + (size_t)b * MAXDET;
    float* out_k = out + (size_t)NBATCH * MAXDET * 6 + (size_t)b * MAXDET * KD;
    const float* kb = kpts + (size_t)b * NANCH * KD;

    for (int t = tid; t < MAXDET; t += TPB) {
        float4 obv = make_float4(0.f, 0.f, 0.f, 0.f);
        float osc = 0.f;
        if (t < nsel) {
            int idx = s.selIdx[t];
            obv = *(const float4*)(bb + (size_t)idx * 4);
            osc = s.selScore[t];
        }
        *(float4*)(out_b + (size_t)t * 4) = obv;
        out_s[t] = osc;
        out_l[t] = 0.0f;
    }
    // Invalid rows gather kpts[b, 0, :] (reference semantics), NOT zeros.
    for (int j = tid; j < MAXDET * KD; j += TPB) {
        int t = j / KD;
        int c = j - t * KD;
        int idx = (t < nsel) ? s.selIdx[t] : 0;
        out_k[j] = kb[(size_t)idx * KD + c];
    }
}

extern "C" void kernel_launch(void* const* d_in, const int* in_sizes, int n_in,
                              void* d_out, int out_size) {
    const float* boxes  = (const float*)d_in[0];
    const float* scores = (const float*)d_in[1];
    const float* kpts   = (const float*)d_in[2];
    float* out = (float*)d_out;

    const int smem = BANDCAP * 8                 // band
                   + MASKW * CHUNK * 8           // maskT
                   + 8 * 8                       // keptw
                   + CHUNK * 16                  // cb4
                   + CHUNK * 4                   // car
                   + NBUCK * 4                   // sfx
                   + 16 * 4 + 16 * 4 + 8 * 4     // blocksum, wball, wchg
                   + 5 * MAXDET * 4              // kept boxes
                   + MAXDET * 4 + MAXDET * 4     // selIdx + selScore
                   + 8 * 4;                      // ctrl

    cudaFuncSetAttribute(nms_pose_kernel,
                         cudaFuncAttributeMaxDynamicSharedMemorySize, smem);
    nms_pose_kernel<<<NBATCH, TPB, smem>>>(boxes, scores, kpts, out);
}

// round 6
// speedup vs baseline: 2.7301x; 1.4064x over previous
#include <cuda_runtime.h>

#define NBATCH 64
#define NANCH  8400
#define KD     51
#define MAXDET 300
#define TPB    512
#define KPT    ((NANCH + TPB - 1) / TPB)   // 17

#define NBUCK   4096
#define KWANT   352
#define FASTCAP 448
#define BANDCAP 1536
#define CHUNK   512
#define MASKW   8

#define SCORE_T 0.001f
#define IOU_T   0.7f

typedef unsigned long long u64;
typedef unsigned int u32;

__device__ __forceinline__ u32 mono(float s) {
    u32 u = __float_as_uint(s);
    return (u & 0x80000000u) ? ~u : (u | 0x80000000u);
}

__device__ __forceinline__ bool sup_exact(float ix, float iy, float a_sel, float a_cand) {
    float inter = fmaxf(ix, 0.0f) * fmaxf(iy, 0.0f);
    float iou = inter / (a_sel + a_cand - inter + 1e-7f);
    return iou > IOU_T;
}

// Branchless main-path pair test; exact reference-form fallback only near the
// decision boundary (same scheme as rounds 1-5, rel_err 0.0).
__device__ __forceinline__ bool pairtest(float4 bj, float aj,
                                         float bx, float by, float bz, float bw, float ar) {
    float ix = fminf(bz, bj.z) - fmaxf(bx, bj.x);
    float iy = fminf(bw, bj.w) - fmaxf(by, bj.y);
    float inter = fmaxf(ix, 0.0f) * fmaxf(iy, 0.0f);
    float denom = aj + ar - inter + 1e-7f;
    float diff  = __fmaf_rn(-IOU_T, denom, inter);     // inter - 0.7*denom
    bool sup;
    if (fabsf(diff) > 1e-4f * denom) sup = (diff > 0.0f);
    else                             sup = sup_exact(ix, iy, aj, ar);
    return sup;
}

struct Sm {
    u64* band; u64* maskT; u64* keptw;
    float4* cb4; float* car;
    u32* sfx; u32* blocksum; u32* wball; u32* wchg;
    float *kx1, *ky1, *kx2, *ky2, *kar;
    int* selIdx; float* selScore; int* ctrl;
};

// Block-wide fixpoint + ranked append. Returns new kept count (uniform).
__device__ __forceinline__ int fixpoint_append(const Sm& s, int tid, int lane, int wid,
                                               bool init, float4 bv, float ar, float sc, int oi,
                                               int kept0)
{
    u32 m = __ballot_sync(0xFFFFFFFFu, init);
    if (lane == 0) s.wball[wid] = m;
    __syncthreads();
    if (tid < MASKW)
        s.keptw[tid] = (u64)s.wball[2 * tid] | ((u64)s.wball[2 * tid + 1] << 32);
    __syncthreads();

    for (int iter = 0; iter < CHUNK; iter++) {
        u64 any = 0ull;
        #pragma unroll
        for (int w = 0; w < MASKW; w++)
            any |= s.maskT[w * CHUNK + tid] & s.keptw[w];
        bool nb = init && (any == 0ull);
        u32 mm = __ballot_sync(0xFFFFFFFFu, nb);
        if (lane == 0) s.wball[wid] = mm;
        __syncthreads();
        if (tid < MASKW) {
            u64 nw = (u64)s.wball[2 * tid] | ((u64)s.wball[2 * tid + 1] << 32);
            u32 ch = 0u;
            if (nw != s.keptw[tid]) { s.keptw[tid] = nw; ch = 1u; }
            s.wchg[tid] = ch;
        }
        __syncthreads();
        u32 c = 0;
        #pragma unroll
        for (int w = 0; w < MASKW; w++) c |= s.wchg[w];
        if (c == 0u) break;
    }

    int totalK = 0;
    #pragma unroll
    for (int w = 0; w < MASKW; w++) totalK += __popcll(s.keptw[w]);
    int take = min(totalK, MAXDET - kept0);

    bool mine = (s.keptw[tid >> 6] >> (tid & 63)) & 1ull;
    if (mine) {
        int rank = 0;
        int wi = tid >> 6;
        #pragma unroll
        for (int w = 0; w < MASKW; w++) if (w < wi) rank += __popcll(s.keptw[w]);
        rank += __popcll(s.keptw[wi] & ((1ull << (tid & 63)) - 1ull));
        if (rank < take) {
            int pos = kept0 + rank;
            s.kx1[pos] = bv.x; s.ky1[pos] = bv.y;
            s.kx2[pos] = bv.z; s.ky2[pos] = bv.w;
            s.kar[pos] = ar;
            s.selIdx[pos] = oi; s.selScore[pos] = sc;
        }
    }
    if (tid == 0) s.ctrl[1] = kept0 + take;
    __syncthreads();
    return s.ctrl[1];
}

__device__ __forceinline__ void set_sup_bit(const Sm& s, int a, int p) {
    int i = max(a, p), j = min(a, p);    // j = higher-score position suppresses i
    atomicOr(&s.maskT[(j >> 6) * CHUNK + i], 1ull << (j & 63));
}

// Balanced circular-distance matrix build. maskT must be zeroed first.
// Each thread t < L tests pairs {t, (t+d) mod L} for d = 1..floor((L-1)/2),
// plus d = L/2 for t < L/2 when L even. Every unordered pair exactly once.
__device__ __forceinline__ void build_matrix_circular(const Sm& s, int t, int L,
                                                      float4 bv, float ar)
{
    if (t >= L) return;
    const float bx = bv.x, by = bv.y, bz = bv.z, bw = bv.w;
    const int nfull = (L - 1) >> 1;

    int c = 0;
    int p = t + 1; if (p >= L) p -= L;
    for (; c + 4 <= nfull; c += 4) {
        int p0 = p;
        int p1 = p0 + 1; if (p1 >= L) p1 -= L;
        int p2 = p1 + 1; if (p2 >= L) p2 -= L;
        int p3 = p2 + 1; if (p3 >= L) p3 -= L;
        float4 B0 = s.cb4[p0], B1 = s.cb4[p1], B2 = s.cb4[p2], B3 = s.cb4[p3];
        float  A0 = s.car[p0], A1 = s.car[p1], A2 = s.car[p2], A3 = s.car[p3];
        bool s0 = pairtest(B0, A0, bx, by, bz, bw, ar);
        bool s1 = pairtest(B1, A1, bx, by, bz, bw, ar);
        bool s2 = pairtest(B2, A2, bx, by, bz, bw, ar);
        bool s3 = pairtest(B3, A3, bx, by, bz, bw, ar);
        if (s0) set_sup_bit(s, t, p0);
        if (s1) set_sup_bit(s, t, p1);
        if (s2) set_sup_bit(s, t, p2);
        if (s3) set_sup_bit(s, t, p3);
        p = p3 + 1; if (p >= L) p -= L;
    }
    for (; c < nfull; c++) {
        if (pairtest(s.cb4[p], s.car[p], bx, by, bz, bw, ar))
            set_sup_bit(s, t, p);
        p = p + 1; if (p >= L) p -= L;
    }
    if (((L & 1) == 0) && t < (L >> 1)) {
        int ph = t + (L >> 1);
        if (pairtest(s.cb4[ph], s.car[ph], bx, by, bz, bw, ar))
            set_sup_bit(s, t, ph);
    }
}

// Generic exact fallback chunk (cold path). Triangular row build.
__device__ int process_chunk_full(const float* bb, const Sm& s,
                                  int tid, int lane, int wid, int cs, int L)
{
    const int kept0 = s.ctrl[1];
    const int ci = cs + tid;
    const bool valid = (ci < L);

    float4 bv = make_float4(0.f, 0.f, 0.f, 0.f);
    float sc = 0.f; int oi = 0;
    if (valid) {
        u64 key = s.band[ci];
        oi = (int)(0xFFFFFFFFu - (u32)(key & 0xFFFFFFFFull));
        sc = __uint_as_float(((u32)(key >> 32)) ^ 0x80000000u);
        bv = *(const float4*)(bb + (size_t)oi * 4);
    }
    float ar = (bv.z - bv.x) * (bv.w - bv.y);

    bool init = valid;
    for (int k = 0; k < kept0 && init; k++) {
        float ix = fminf(bv.z, s.kx2[k]) - fmaxf(bv.x, s.kx1[k]);
        float iy = fminf(bv.w, s.ky2[k]) - fmaxf(bv.y, s.ky1[k]);
        if (sup_exact(ix, iy, s.kar[k], ar)) init = false;
    }

    s.cb4[tid] = bv; s.car[tid] = ar;
    // zero mask rows
    #pragma unroll
    for (int w = 0; w < MASKW; w++) s.maskT[w * CHUNK + tid] = 0ull;
    __syncthreads();

    int C = min(L - cs, CHUNK);
    build_matrix_circular(s, tid, C, bv, ar);
    __syncthreads();

    return fixpoint_append(s, tid, lane, wid, init, bv, ar, sc, oi, kept0);
}

__global__ __launch_bounds__(TPB, 1)
void nms_pose_kernel(const float* __restrict__ boxes, const float* __restrict__ scores,
                     const float* __restrict__ kpts, float* __restrict__ out)
{
    extern __shared__ unsigned char smraw[];
    Sm s;
    s.band  = (u64*)smraw;                        // [BANDCAP]
    s.maskT = s.band + BANDCAP;                   // [MASKW*CHUNK]
    s.keptw = s.maskT + MASKW * CHUNK;            // [8]
    s.cb4   = (float4*)(s.keptw + 8);             // [CHUNK]
    s.car   = (float*)(s.cb4 + CHUNK);            // [CHUNK]
    s.sfx   = (u32*)(s.car + CHUNK);              // [NBUCK]
    s.blocksum = s.sfx + NBUCK;                   // [16]
    s.wball    = s.blocksum + 16;                 // [16]
    s.wchg     = s.wball + 16;                    // [8]
    s.kx1 = (float*)(s.wchg + 8);
    s.ky1 = s.kx1 + MAXDET; s.kx2 = s.ky1 + MAXDET;
    s.ky2 = s.kx2 + MAXDET; s.kar = s.ky2 + MAXDET;
    s.selIdx   = (int*)(s.kar + MAXDET);
    s.selScore = (float*)(s.selIdx + MAXDET);
    s.ctrl     = (int*)(s.selScore + MAXDET);     // [0]=cnt [1]=kept [2]=fastok [3]=tb

    const int b = blockIdx.x, tid = threadIdx.x, lane = tid & 31, wid = tid >> 5;
    const float* bb = boxes  + (size_t)b * NANCH * 4;
    const float* ss = scores + (size_t)b * NANCH;

    // ---------- Phase A: histogram ----------
    for (int i = tid; i < NBUCK; i += TPB) s.sfx[i] = 0u;
    if (tid == 0) s.ctrl[1] = 0;
    __syncthreads();

    int Lfast = 0;
    int fastok, tb;
    {
        float rs[KPT]; int rbk[KPT];
        #pragma unroll
        for (int k = 0; k < KPT; k++) {
            int idx = tid + k * TPB;
            float sv = (idx < NANCH) ? ss[idx] : 0.0f;
            rs[k] = sv; int bk = -1;
            if (idx < NANCH && sv > SCORE_T) {
                bk = min((int)(sv * (float)NBUCK), NBUCK - 1);
                atomicAdd(&s.sfx[bk], 1u);
            }
            rbk[k] = bk;
        }
        __syncthreads();

        // ---------- Phase B: suffix sums ----------
        {
            u32 lsum[8]; u32 run = 0;
            const int base = tid * 8;                 // NBUCK == TPB*8
            #pragma unroll
            for (int j = 7; j >= 0; j--) { run += s.sfx[base + j]; lsum[j] = run; }
            u32 x = run;
            #pragma unroll
            for (int off = 1; off < 32; off <<= 1) {
                u32 o = __shfl_down_sync(0xFFFFFFFFu, x, off);
                if (lane + off < 32) x += o;
            }
            if (lane == 0) s.blocksum[wid] = x;
            __syncthreads();
            u32 woff = 0;
            for (int w = wid + 1; w < TPB / 32; w++) woff += s.blocksum[w];
            u32 excl = woff + (x - run);
            #pragma unroll
            for (int j = 0; j < 8; j++) s.sfx[base + j] = excl + lsum[j];
            __syncthreads();
        }

        // ---------- Phase C: pick fast band [tb, NBUCK), count <= FASTCAP ----------
        if (tid == 0) {
            u32 total = s.sfx[0];
            int fok = 0, t0 = NBUCK;
            if (total > 0u) {
                u32 want = total < (u32)KWANT ? total : (u32)KWANT;
                int lo = 0, hi = NBUCK - 1; t0 = 0;
                while (lo <= hi) {
                    int m = (lo + hi) >> 1;
                    if (s.sfx[m] >= want) { t0 = m; lo = m + 1; } else hi = m - 1;
                }
                if (s.sfx[t0] > (u32)FASTCAP) {
                    int lo2 = t0 + 1, hi2 = NBUCK - 1, nb = NBUCK;
                    while (lo2 <= hi2) {
                        int m = (lo2 + hi2) >> 1;
                        if (s.sfx[m] <= (u32)FASTCAP) { nb = m; hi2 = m - 1; }
                        else lo2 = m + 1;
                    }
                    t0 = nb;
                }
                if (t0 < NBUCK && s.sfx[t0] > 0u && s.sfx[t0] <= (u32)FASTCAP) fok = 1;
            }
            s.ctrl[2] = fok; s.ctrl[3] = t0;
        }
        __syncthreads();
        fastok = s.ctrl[2];
        tb = s.ctrl[3];

        // ---------- Phase D: scan-compacted gather (no atomics) ----------
        {
            int cnt = 0;
            #pragma unroll
            for (int k = 0; k < KPT; k++) if (rbk[k] >= tb) cnt++;
            u32 x = (u32)cnt;
            #pragma unroll
            for (int off = 1; off < 32; off <<= 1) {
                u32 o = __shfl_up_sync(0xFFFFFFFFu, x, off);
                if (lane >= off) x += o;
            }
            if (lane == 31) s.blocksum[wid] = x;
            __syncthreads();
            u32 wbase = 0, total = 0;
            #pragma unroll
            for (int w = 0; w < TPB / 32; w++) {
                u32 v = s.blocksum[w];
                if (w < wid) wbase += v;
                total += v;
            }
            if (fastok) {
                int ofs = (int)(wbase + x) - cnt;
                #pragma unroll
                for (int k = 0; k < KPT; k++) {
                    if (rbk[k] >= tb) {
                        int idx = tid + k * TPB;
                        s.band[ofs++] = ((u64)mono(rs[k]) << 32) |
                                        (u64)(0xFFFFFFFFu - (u32)idx);
                    }
                }
                Lfast = (int)total;      // == sfx[tb] <= FASTCAP
            }
            __syncthreads();
        }
    }   // rs/rbk dead

    int kept = 0;

    if (fastok) {
        const int L = Lfast;
        if (tid >= L) s.band[tid] = 0ull;      // pad (sorts to tail)
        __syncthreads();

        // ---------- Phase E: register bitonic sort (descending), P = 512 ----------
        u64 v = s.band[tid];
        #pragma unroll
        for (int k = 2; k <= 32; k <<= 1) {
            #pragma unroll
            for (int j = k >> 1; j > 0; j >>= 1) {
                u64 o = __shfl_xor_sync(0xFFFFFFFFu, v, j);
                bool lower = (tid & j) == 0;
                bool desc  = (tid & k) == 0;
                bool takeMax = (desc == lower);
                v = takeMax ? (v > o ? v : o) : (v > o ? o : v);
            }
        }
        #pragma unroll
        for (int k = 64; k <= 512; k <<= 1) {
            for (int j = k >> 1; j >= 32; j >>= 1) {
                s.band[tid] = v;
                __syncthreads();
                u64 o = s.band[tid ^ j];
                __syncthreads();
                bool lower = (tid & j) == 0;
                bool desc  = (tid & k) == 0;
                bool takeMax = (desc == lower);
                v = takeMax ? (v > o ? v : o) : (v > o ? o : v);
            }
            #pragma unroll
            for (int j = 16; j > 0; j >>= 1) {
                u64 o = __shfl_xor_sync(0xFFFFFFFFu, v, j);
                bool lower = (tid & j) == 0;
                bool desc  = (tid & k) == 0;
                bool takeMax = (desc == lower);
                v = takeMax ? (v > o ? v : o) : (v > o ? o : v);
            }
        }

        // ---------- Phase F: decode, matrix, fixpoint ----------
        const bool valid = (tid < L);
        float4 bv = make_float4(0.f, 0.f, 0.f, 0.f);
        float sc = 0.f; int oi = 0;
        if (valid) {
            oi = (int)(0xFFFFFFFFu - (u32)(v & 0xFFFFFFFFull));
            sc = __uint_as_float(((u32)(v >> 32)) ^ 0x80000000u);
            bv = *(const float4*)(bb + (size_t)oi * 4);
        }
        float ar = (bv.z - bv.x) * (bv.w - bv.y);
        s.cb4[tid] = bv; s.car[tid] = ar;
        #pragma unroll
        for (int w = 0; w < MASKW; w++) s.maskT[w * CHUNK + tid] = 0ull;
        __syncthreads();

        build_matrix_circular(s, tid, L, bv, ar);
        __syncthreads();

        kept = fixpoint_append(s, tid, lane, wid, valid, bv, ar, sc, oi, 0);
    }

    // ---------- Phase G: exact generic fallback (cold) ----------
    if (kept < MAXDET) {
        int curTop = fastok ? tb : NBUCK;
        while (kept < MAXDET) {
            u32 proc  = (curTop < NBUCK) ? s.sfx[curTop] : 0u;
            u32 total = s.sfx[0];
            u32 remaining = total - proc;
            if (remaining == 0u) break;

            if (tid == 0) {
                u32 want = remaining < (u32)FASTCAP ? remaining : (u32)FASTCAP;
                u32 target = proc + want;
                int tb2 = 0;
                {
                    int lo = 0, hi = curTop - 1;
                    while (lo <= hi) {
                        int mid = (lo + hi) >> 1;
                        if (s.sfx[mid] >= target) { tb2 = mid; lo = mid + 1; }
                        else hi = mid - 1;
                    }
                }
                if (s.sfx[tb2] - proc > (u32)BANDCAP) {
                    u32 t2 = proc + BANDCAP;
                    int lo = tb2 + 1, hi = curTop - 1, nb2 = curTop - 1;
                    while (lo <= hi) {
                        int mid = (lo + hi) >> 1;
                        if (s.sfx[mid] <= t2) { nb2 = mid; hi = mid - 1; }
                        else lo = mid + 1;
                    }
                    tb2 = nb2;
                }
                s.ctrl[3] = tb2; s.ctrl[0] = 0;
            }
            __syncthreads();
            const int tb2 = s.ctrl[3];

            #pragma unroll
            for (int k = 0; k < KPT; k++) {
                int idx = tid + k * TPB;
                if (idx < NANCH) {
                    float sv = ss[idx];
                    if (sv > SCORE_T) {
                        int bk = min((int)(sv * (float)NBUCK), NBUCK - 1);
                        if (bk >= tb2 && bk < curTop) {
                            int pos = atomicAdd(&s.ctrl[0], 1);
                            if (pos < BANDCAP)
                                s.band[pos] = ((u64)mono(sv) << 32) |
                                              (u64)(0xFFFFFFFFu - (u32)idx);
                        }
                    }
                }
            }
            __syncthreads();
            int Lb = min(s.ctrl[0], BANDCAP);

            int P = 1; while (P < Lb) P <<= 1; if (P < 2) P = 2;
            for (int i = Lb + tid; i < P; i += TPB) s.band[i] = 0ull;
            __syncthreads();
            for (int ksz = 2; ksz <= P; ksz <<= 1) {
                for (int j = ksz >> 1; j > 0; j >>= 1) {
                    for (int t = tid; t < P; t += TPB) {
                        int p = t ^ j;
                        if (p > t) {
                            u64 a = s.band[t], c = s.band[p];
                            bool descBlock = ((t & ksz) == 0);
                            if (descBlock ? (a < c) : (a > c)) { s.band[t] = c; s.band[p] = a; }
                        }
                    }
                    __syncthreads();
                }
            }

            for (int cs = 0; cs < Lb && kept < MAXDET; cs += CHUNK)
                kept = process_chunk_full(bb, s, tid, lane, wid, cs, Lb);

            curTop = tb2;
            __syncthreads();
        }
    }
    __syncthreads();
    const int nsel = s.ctrl[1];

    // ---------- Phase H: outputs ----------
    float* out_b = out + (size_t)b * MAXDET * 4;
    float* out_s = out + (size_t)NBATCH * MAXDET * 4 + (size_t)b * MAXDET;
    float* out_l = out + (size_t)NBATCH * MAXDET * 5 + (size_t)b * MAXDET;
    float* out_k = out + (size_t)NBATCH * MAXDET * 6 + (size_t)b * MAXDET * KD;
    const float* kb = kpts + (size_t)b * NANCH * KD;

    for (int t = tid; t < MAXDET; t += TPB) {
        float4 obv = make_float4(0.f, 0.f, 0.f, 0.f);
        float osc = 0.f;
        if (t < nsel) {
            int idx = s.selIdx[t];
            obv = *(const float4*)(bb + (size_t)idx * 4);
            osc = s.selScore[t];
        }
        *(float4*)(out_b + (size_t)t * 4) = obv;
        out_s[t] = osc;
        out_l[t] = 0.0f;
    }
    // Invalid rows gather kpts[b, 0, :] (reference semantics), NOT zeros.
    for (int j = tid; j < MAXDET * KD; j += TPB) {
        int t = j / KD;
        int c = j - t * KD;
        int idx = (t < nsel) ? s.selIdx[t] : 0;
        out_k[j] = kb[(size_t)idx * KD + c];
    }
}

extern "C" void kernel_launch(void* const* d_in, const int* in_sizes, int n_in,
                              void* d_out, int out_size) {
    const float* boxes  = (const float*)d_in[0];
    const float* scores = (const float*)d_in[1];
    const float* kpts   = (const float*)d_in[2];
    float* out = (float*)d_out;

    const int smem = BANDCAP * 8                 // band
                   + MASKW * CHUNK * 8           // maskT
                   + 8 * 8                       // keptw
                   + CHUNK * 16                  // cb4
                   + CHUNK * 4                   // car
                   + NBUCK * 4                   // sfx
                   + 16 * 4 + 16 * 4 + 8 * 4     // blocksum, wball, wchg
                   + 5 * MAXDET * 4              // kept boxes
                   + MAXDET * 4 + MAXDET * 4     // selIdx + selScore
                   + 8 * 4;                      // ctrl

    cudaFuncSetAttribute(nms_pose_kernel,
                         cudaFuncAttributeMaxDynamicSharedMemorySize, smem);
    nms_pose_kernel<<<NBATCH, TPB, smem>>>(boxes, scores, kpts, out);
}